// round 5
// baseline (speedup 1.0000x reference)
#include <cuda_runtime.h>
#include <cstdint>
#include <cstddef>

// TemporalAttention: x (B,T,C,H,W) -> per-pixel attention over T.
//   Q = Wq x + bq (D=64), K = Wk x + bk (D=64), S = QK^T/8, A = softmax(S)
//   out = (A @ X) @ Wv^T + bv      (valid because softmax rows sum to 1)
//
// Fused single kernel: 16 pixels per CTA, 512 threads (16 warps for latency
// hiding at occ=1-CTA), two 128x128x128 register-blocked fp32 GEMMs per CTA
// with 8x4 per-thread tiles.

namespace {
constexpr int kT   = 8;
constexpr int kC   = 128;
constexpr int kHW  = 96 * 96;          // 9216
constexpr int kPIX = 16;               // pixels per CTA
constexpr int kLD  = 136;              // padded row length for conflict relief
constexpr int kTHREADS = 512;
// smem: buf1[128*136] (Wqk^T -> QK -> Ys), buf2[128*136] (Wv^T -> out staging),
//       Xs[128*128], Ssm[1024]
constexpr int kSMEM_FLOATS = 2 * 128 * kLD + 128 * 128 + 1024;
}

__global__ __launch_bounds__(kTHREADS, 1)
void ta_fused(const float* __restrict__ x,
              const float* __restrict__ Wq, const float* __restrict__ bq,
              const float* __restrict__ Wk, const float* __restrict__ bk,
              const float* __restrict__ Wv, const float* __restrict__ bv,
              float* __restrict__ out)
{
    extern __shared__ float sm[];
    float* buf1 = sm;                       // 128 x kLD
    float* buf2 = sm + 128 * kLD;           // 128 x kLD
    float* Xs   = sm + 2 * 128 * kLD;       // [c][m], m = p*8 + t, 128x128
    float* Ssm  = Xs + 128 * 128;           // attn weights, 16*8*8

    const int tid = threadIdx.x;
    const int tx  = tid & 31;               // n-tile: 4 contiguous cols
    const int ty  = tid >> 5;               // m-tile: 4+4 split rows (== warp id)
    const int b   = blockIdx.y;
    const int pix0 = blockIdx.x * kPIX;

    // per-thread bias registers for this thread's 4 n-columns
    float bqk[4], bvr[4];
#pragma unroll
    for (int j = 0; j < 4; ++j) {
        int n = tx * 4 + j;
        bqk[j] = (n < 64) ? bq[n] : bk[n - 64];
        bvr[j] = bv[n];
    }

    // ---- stage weights K-major into smem ----
    // buf1[c][n] : n<64 -> Wq[n][c], n>=64 -> Wk[n-64][c]
    for (int i = tid; i < 64 * kC; i += kTHREADS) {
        int n = i >> 7, c = i & 127;
        buf1[c * kLD + n]      = Wq[i];
        buf1[c * kLD + 64 + n] = Wk[i];
    }
    // buf2[c][e] = Wv[e][c]
    for (int i = tid; i < kC * kC; i += kTHREADS) {
        int e = i >> 7, c = i & 127;
        buf2[c * kLD + e] = Wv[i];
    }
    // ---- stage x tile: Xs[c][p*8 + t] = x[b,t,c,pix0+p] ----
    const float* xb = x + (size_t)b * (kT * kC * kHW) + pix0;
    for (int i = tid; i < kT * kC * kPIX; i += kTHREADS) {
        int p  = i & 15;
        int tc = i >> 4;                    // t*128 + c
        int c  = tc & 127;
        Xs[c * 128 + p * 8 + (tc >> 7)] = xb[(size_t)tc * kHW + p];
    }
    __syncthreads();

    // ================= GEMM1: QK[m][n] = sum_c Xs[c][m] * Wqk[c][n] =========
    // per-thread 8(m) x 4(n); A-loads are warp-uniform broadcasts.
    float acc[8][4];
#pragma unroll
    for (int i = 0; i < 8; ++i)
#pragma unroll
        for (int j = 0; j < 4; ++j) acc[i][j] = 0.f;

#pragma unroll 2
    for (int k = 0; k < 128; ++k) {
        float4 A0 = *(const float4*)&Xs[k * 128 + ty * 4];
        float4 A1 = *(const float4*)&Xs[k * 128 + 64 + ty * 4];
        float4 B0 = *(const float4*)&buf1[k * kLD + tx * 4];
        float a[8]  = {A0.x, A0.y, A0.z, A0.w, A1.x, A1.y, A1.z, A1.w};
        float bb[4] = {B0.x, B0.y, B0.z, B0.w};
#pragma unroll
        for (int i = 0; i < 8; ++i)
#pragma unroll
            for (int j = 0; j < 4; ++j) acc[i][j] += a[i] * bb[j];
    }
    __syncthreads();

    // store Q,K (+bias) into buf1 as QK[m][n] (m-major, padded rows)
#pragma unroll
    for (int i = 0; i < 8; ++i) {
        int m = (i < 4) ? (ty * 4 + i) : (64 + ty * 4 + i - 4);
#pragma unroll
        for (int j = 0; j < 4; ++j)
            buf1[m * kLD + tx * 4 + j] = acc[i][j] + bqk[j];
    }
    __syncthreads();

    // ================= scores + softmax ====================================
    // 16 warps, 1 pixel/warp; per pixel 64 score entries in two t-halves
    // (t = (lane>>3) + 4*half, s = lane&7); 8-lane shfl groups reduce over s.
    {
        const int p = tid >> 5, lane = tid & 31;
        const int tlo = lane >> 3, s = lane & 7;
#pragma unroll
        for (int half = 0; half < 2; ++half) {
            int t = tlo + half * 4;
            const float* qr = &buf1[(p * 8 + t) * kLD];
            const float* kr = &buf1[(p * 8 + s) * kLD + 64];
            float dot = 0.f;
#pragma unroll
            for (int d = 0; d < 64; d += 4) {
                float4 q4 = *(const float4*)&qr[d];
                float4 k4 = *(const float4*)&kr[d];
                dot += q4.x * k4.x + q4.y * k4.y + q4.z * k4.z + q4.w * k4.w;
            }
            dot *= 0.125f;   // 1/sqrt(64)
            float mx = dot;
#pragma unroll
            for (int o = 1; o < 8; o <<= 1)
                mx = fmaxf(mx, __shfl_xor_sync(0xffffffffu, mx, o));
            float e = __expf(dot - mx);
            float sum = e;
#pragma unroll
            for (int o = 1; o < 8; o <<= 1)
                sum += __shfl_xor_sync(0xffffffffu, sum, o);
            Ssm[(p * 8 + t) * 8 + s] = e / sum;
        }
    }
    __syncthreads();

    // ========== Y[c][m] = sum_s attn[p,t,s] * Xs[c][p*8+s]  (into buf1) =====
    {
        const int m  = tid & 127;           // p*8 + t
        const int c0 = (tid >> 7) * 32;     // 4 threads per m, 32 c's each
        const int p  = m >> 3;
        float a[8];
#pragma unroll
        for (int s2 = 0; s2 < 8; ++s2) a[s2] = Ssm[m * 8 + s2];
        for (int c = c0; c < c0 + 32; ++c) {
            const float4* xr = (const float4*)&Xs[c * 128 + p * 8];
            float4 x0 = xr[0], x1 = xr[1];
            buf1[c * kLD + m] =
                a[0] * x0.x + a[1] * x0.y + a[2] * x0.z + a[3] * x0.w +
                a[4] * x1.x + a[5] * x1.y + a[6] * x1.z + a[7] * x1.w;
        }
    }
    __syncthreads();

    // ========== GEMM3: out[m][e] = sum_c Ys[c][m] * Wv[e][c] ================
#pragma unroll
    for (int i = 0; i < 8; ++i)
#pragma unroll
        for (int j = 0; j < 4; ++j) acc[i][j] = 0.f;

#pragma unroll 2
    for (int k = 0; k < 128; ++k) {
        float4 A0 = *(const float4*)&buf1[k * kLD + ty * 4];
        float4 A1 = *(const float4*)&buf1[k * kLD + 64 + ty * 4];
        float4 B0 = *(const float4*)&buf2[k * kLD + tx * 4];
        float a[8]  = {A0.x, A0.y, A0.z, A0.w, A1.x, A1.y, A1.z, A1.w};
        float bb[4] = {B0.x, B0.y, B0.z, B0.w};
#pragma unroll
        for (int i = 0; i < 8; ++i)
#pragma unroll
            for (int j = 0; j < 4; ++j) acc[i][j] += a[i] * bb[j];
    }
    __syncthreads();

    // stage result (+bias) into buf2 as Os[(t*128+e)*16 + p] for coalesced stores
#pragma unroll
    for (int i = 0; i < 8; ++i) {
        int m = (i < 4) ? (ty * 4 + i) : (64 + ty * 4 + i - 4);
        int p = m >> 3, t = m & 7;
#pragma unroll
        for (int j = 0; j < 4; ++j) {
            int n = tx * 4 + j;
            buf2[(t * 128 + n) * 16 + p] = acc[i][j] + bvr[j];
        }
    }
    __syncthreads();

    // ========== coalesced gmem write: out[b,t,e,pix0+p] ======================
    {
        float* ob = out + (size_t)b * (kT * kC * kHW) + pix0;
        const int p = tid & 15, g = tid >> 4;   // g in [0,32)
#pragma unroll 4
        for (int it = 0; it < 32; ++it) {
            int q = it * 32 + g;            // q = t*128 + e
            ob[(size_t)q * kHW + p] = buf2[q * 16 + p];
        }
    }
}

extern "C" void kernel_launch(void* const* d_in, const int* in_sizes, int n_in,
                              void* d_out, int out_size)
{
    const float* x  = (const float*)d_in[0];
    const float* Wq = (const float*)d_in[1];
    const float* bq = (const float*)d_in[2];
    const float* Wk = (const float*)d_in[3];
    const float* bk = (const float*)d_in[4];
    const float* Wv = (const float*)d_in[5];
    const float* bv = (const float*)d_in[6];
    float* out = (float*)d_out;

    const int B = in_sizes[0] / (kT * kC * kHW);
    const size_t smem = kSMEM_FLOATS * sizeof(float);
    cudaFuncSetAttribute(ta_fused, cudaFuncAttributeMaxDynamicSharedMemorySize,
                         (int)smem);
    dim3 grid(kHW / kPIX, B);
    ta_fused<<<grid, kTHREADS, smem>>>(x, Wq, bq, Wk, bk, Wv, bv, out);
}

// round 8
// speedup vs baseline: 1.7059x; 1.7059x over previous
#include <cuda_runtime.h>
#include <cuda_bf16.h>
#include <cstdint>
#include <cstddef>

// TemporalAttention via warp-level bf16 mma.sync (HMMA) — base-arch ISA only
// (harness compiles for sm_103 without the 'a' feature set, so no tcgen05).
//
// Per CTA: 16 pixels, rows m = p*8+t in [0,128).
//   GEMM1: D1[m][n] = X[m][:]·Wqk[n][:]   (n<64 -> Q col, n>=64 -> K col)
//   scores/softmax fully in registers via warp shuffles (each warp's m16 tile
//   holds 2 complete pixels; fragment row = t).
//   GEMM2: D2[m][e] = X[m][:]·Wv[e][:]    (V), then out = attn@V + bv in regs.
// Both GEMMs: bf16 hi/lo 3-term split (AhiBhi + AloBhi + AhiBlo), fp32 accum.

namespace {
constexpr int kT = 8, kC = 128, kHW = 96 * 96, kPIX = 16, kTHREADS = 256;
constexpr int kSA = 272;                 // row stride in bytes (136 bf16)
// smem regions (bytes)
constexpr int A_HI   = 0;
constexpr int A_LO   = 34816;
constexpr int BQK_HI = 69632;            // aliases: x-transpose scratch
constexpr int BQK_LO = 104448;
constexpr int BV_HI  = 139264;
constexpr int BV_LO  = 174080;
constexpr int BIAS   = 208896;           // 256 floats: bq | bk | bv
constexpr int kSMEM  = 209920;
// out staging aliases A region (max idx 16411 floats = 65644 B < 69632)
}

__device__ __forceinline__ uint32_t s2u(const void* p) {
    uint32_t a;
    asm("{ .reg .u64 t; cvta.to.shared.u64 t, %1; cvt.u32.u64 %0, t; }"
        : "=r"(a) : "l"(p));
    return a;
}
__device__ __forceinline__ void ldsm4(uint32_t& r0, uint32_t& r1, uint32_t& r2,
                                      uint32_t& r3, uint32_t addr) {
    asm volatile("ldmatrix.sync.aligned.m8n8.x4.shared.b16 {%0,%1,%2,%3}, [%4];"
                 : "=r"(r0), "=r"(r1), "=r"(r2), "=r"(r3) : "r"(addr));
}
__device__ __forceinline__ void mma16816(float* d, uint32_t a0, uint32_t a1,
                                         uint32_t a2, uint32_t a3,
                                         uint32_t b0, uint32_t b1) {
    asm volatile(
        "mma.sync.aligned.m16n8k16.row.col.f32.bf16.bf16.f32 "
        "{%0,%1,%2,%3}, {%4,%5,%6,%7}, {%8,%9}, {%0,%1,%2,%3};"
        : "+f"(d[0]), "+f"(d[1]), "+f"(d[2]), "+f"(d[3])
        : "r"(a0), "r"(a1), "r"(a2), "r"(a3), "r"(b0), "r"(b1));
}
__device__ __forceinline__ void split2(float v0, float v1, uint32_t& hw,
                                       uint32_t& lw) {
    __nv_bfloat16 h0 = __float2bfloat16(v0), h1 = __float2bfloat16(v1);
    float r0 = v0 - __bfloat162float(h0), r1 = v1 - __bfloat162float(h1);
    __nv_bfloat16 l0 = __float2bfloat16(r0), l1 = __float2bfloat16(r1);
    hw = ((uint32_t)__bfloat16_as_ushort(h1) << 16) | __bfloat16_as_ushort(h0);
    lw = ((uint32_t)__bfloat16_as_ushort(l1) << 16) | __bfloat16_as_ushort(l0);
}

// one 128(m) x 128(n) x 128(k) 3-term split GEMM; warp wid owns rows wid*16..+15
__device__ __forceinline__ void do_gemm(uint32_t aHi, uint32_t aLo,
                                        uint32_t bHi, uint32_t bLo,
                                        int lane, int wid, float d[16][4]) {
#pragma unroll
    for (int nt = 0; nt < 16; ++nt)
#pragma unroll
        for (int r = 0; r < 4; ++r) d[nt][r] = 0.f;

    const uint32_t abyte = (uint32_t)(wid * 16 + (lane & 15)) * kSA +
                           ((lane >> 4) * 16);
    const int bro = (lane & 7) + (((lane >> 4) & 1) * 8);
    const uint32_t bkh = (uint32_t)(((lane >> 3) & 1) * 16);

#pragma unroll
    for (int ks = 0; ks < 8; ++ks) {
        uint32_t ao = abyte + ks * 32;
        uint32_t ah0, ah1, ah2, ah3, al0, al1, al2, al3;
        ldsm4(ah0, ah1, ah2, ah3, aHi + ao);
        ldsm4(al0, al1, al2, al3, aLo + ao);
#pragma unroll
        for (int ntp = 0; ntp < 8; ++ntp) {
            uint32_t bo = (uint32_t)(ntp * 16 + bro) * kSA + ks * 32 + bkh;
            uint32_t h0, h1, h2, h3, l0, l1, l2, l3;
            ldsm4(h0, h1, h2, h3, bHi + bo);
            ldsm4(l0, l1, l2, l3, bLo + bo);
            mma16816(d[2 * ntp], ah0, ah1, ah2, ah3, h0, h1);
            mma16816(d[2 * ntp], al0, al1, al2, al3, h0, h1);
            mma16816(d[2 * ntp], ah0, ah1, ah2, ah3, l0, l1);
            mma16816(d[2 * ntp + 1], ah0, ah1, ah2, ah3, h2, h3);
            mma16816(d[2 * ntp + 1], al0, al1, al2, al3, h2, h3);
            mma16816(d[2 * ntp + 1], ah0, ah1, ah2, ah3, l2, l3);
        }
    }
}

__global__ __launch_bounds__(kTHREADS, 1)
void ta_mma(const float* __restrict__ x,
            const float* __restrict__ Wq, const float* __restrict__ bq,
            const float* __restrict__ Wk, const float* __restrict__ bk,
            const float* __restrict__ Wv, const float* __restrict__ bv,
            float* __restrict__ out)
{
    extern __shared__ char smem[];
    const uint32_t sb = s2u(smem);
    float* scratch = (float*)(smem + BQK_HI);
    float* outst   = (float*)(smem);
    float* bias_sm = (float*)(smem + BIAS);

    const int tid = threadIdx.x, wid = tid >> 5, lane = tid & 31;
    const int b = blockIdx.y, pix0 = blockIdx.x * kPIX;

    // ---- phase 1: x -> scratch (coalesced reads, rotated layout) ----------
    const float* xb = x + (size_t)b * (kT * kC * kHW) + pix0;
    for (int i = tid; i < kT * kC * kPIX; i += kTHREADS) {
        int p = i & 15, tc = i >> 4;            // tc = t*128 + c
        int c = tc & 127, t = tc >> 7;
        scratch[tc * 16 + ((p + (c >> 1)) & 15) + t * 4] =
            xb[(size_t)tc * kHW + p];
    }
    // ---- Bv staging + bias (scratch-free regions) -------------------------
    for (int i = tid; i < 128 * 64; i += kTHREADS) {
        int n = i >> 6, cp = i & 63;
        float2 v = *(const float2*)(Wv + n * kC + cp * 2);
        uint32_t hw, lw;
        split2(v.x, v.y, hw, lw);
        *(uint32_t*)(smem + BV_HI + n * kSA + cp * 4) = hw;
        *(uint32_t*)(smem + BV_LO + n * kSA + cp * 4) = lw;
    }
    bias_sm[tid] = (tid < 64) ? bq[tid]
                 : (tid < 128) ? bk[tid - 64] : bv[tid - 128];
    __syncthreads();

    // ---- phase 2: scratch -> A hi/lo (bf16, transposed to [m][c]) ---------
    for (int i = tid; i < 128 * 64; i += kTHREADS) {
        int cp = i & 63, m = i >> 6;
        int t = m & 7, p = m >> 3;
        int base = (t * 128 + 2 * cp) * 16 + t * 4;
        int prot = (p + cp) & 15;
        float f0 = scratch[base + prot];
        float f1 = scratch[base + 16 + prot];
        uint32_t hw, lw;
        split2(f0, f1, hw, lw);
        *(uint32_t*)(smem + A_HI + m * kSA + cp * 4) = hw;
        *(uint32_t*)(smem + A_LO + m * kSA + cp * 4) = lw;
    }
    __syncthreads();

    // ---- Bqk staging (overwrites scratch) ---------------------------------
    for (int i = tid; i < 128 * 64; i += kTHREADS) {
        int n = i >> 6, cp = i & 63;
        const float* src = (n < 64) ? (Wq + n * kC) : (Wk + (n - 64) * kC);
        float2 v = *(const float2*)(src + cp * 2);
        uint32_t hw, lw;
        split2(v.x, v.y, hw, lw);
        *(uint32_t*)(smem + BQK_HI + n * kSA + cp * 4) = hw;
        *(uint32_t*)(smem + BQK_LO + n * kSA + cp * 4) = lw;
    }
    __syncthreads();

    // ---- GEMM1: QK ---------------------------------------------------------
    float d1[16][4];
    do_gemm(sb + A_HI, sb + A_LO, sb + BQK_HI, sb + BQK_LO, lane, wid, d1);

    // ---- scores + softmax (in registers, warp owns pixels 2w, 2w+1) -------
    const int l4 = lane & 3, lg = lane >> 2;    // lg = t (fragment row)
    float attn0[8], attn1[8];
#pragma unroll
    for (int pi = 0; pi < 2; ++pi) {
        float qv[16], kv[16];
#pragma unroll
        for (int nt = 0; nt < 8; ++nt)
#pragma unroll
            for (int j = 0; j < 2; ++j) {
                int c = nt * 8 + l4 * 2 + j;
                qv[nt * 2 + j] = d1[nt][pi * 2 + j] + bias_sm[c];
                kv[nt * 2 + j] = d1[8 + nt][pi * 2 + j] + bias_sm[64 + c];
            }
        float sc[8];
#pragma unroll
        for (int s = 0; s < 8; ++s) {
            int src = s * 4 + l4;
            float a = 0.f;
#pragma unroll
            for (int idx = 0; idx < 16; ++idx)
                a += qv[idx] * __shfl_sync(0xffffffffu, kv[idx], src);
            a += __shfl_xor_sync(0xffffffffu, a, 1);
            a += __shfl_xor_sync(0xffffffffu, a, 2);
            sc[s] = a * 0.125f;                 // 1/sqrt(64)
        }
        float mx = sc[0];
#pragma unroll
        for (int s = 1; s < 8; ++s) mx = fmaxf(mx, sc[s]);
        float sum = 0.f, e[8];
#pragma unroll
        for (int s = 0; s < 8; ++s) { e[s] = __expf(sc[s] - mx); sum += e[s]; }
        float inv = 1.f / sum;
#pragma unroll
        for (int s = 0; s < 8; ++s)
            (pi == 0 ? attn0 : attn1)[s] = e[s] * inv;
    }

    // ---- GEMM2: V ----------------------------------------------------------
    float d2[16][4];
    do_gemm(sb + A_HI, sb + A_LO, sb + BV_HI, sb + BV_LO, lane, wid, d2);
    __syncthreads();                            // A region dead -> out staging

    // ---- mix attn@V + bv, stage rotated for coalesced stores --------------
    const int p0 = wid * 2, p1 = wid * 2 + 1;
#pragma unroll
    for (int nt = 0; nt < 16; ++nt)
#pragma unroll
        for (int j = 0; j < 2; ++j) {
            int c = nt * 8 + l4 * 2 + j;
            float o0 = bias_sm[128 + c], o1 = o0;
#pragma unroll
            for (int s = 0; s < 8; ++s) {
                int src = s * 4 + l4;
                o0 += attn0[s] * __shfl_sync(0xffffffffu, d2[nt][j], src);
                o1 += attn1[s] * __shfl_sync(0xffffffffu, d2[nt][2 + j], src);
            }
            int base = (lg * 128 + c) * 16 + lg * 4;
            int rot = (c >> 1) & 15;
            outst[base + ((p0 + rot) & 15)] = o0;
            outst[base + ((p1 + rot) & 15)] = o1;
        }
    __syncthreads();

    // ---- coalesced gmem store: out[b,t,e,pix0+p] --------------------------
    {
        float* ob = out + (size_t)b * (kT * kC * kHW) + pix0;
        const int sp = tid & 15, g = tid >> 4;
#pragma unroll 4
        for (int it = 0; it < 64; ++it) {
            int q = it * 16 + g;                // t*128 + e
            int t = q >> 7, c = q & 127;
            ob[(size_t)q * kHW + sp] =
                outst[q * 16 + ((sp + (c >> 1)) & 15) + t * 4];
        }
    }
}

extern "C" void kernel_launch(void* const* d_in, const int* in_sizes, int n_in,
                              void* d_out, int out_size)
{
    const float* x  = (const float*)d_in[0];
    const float* Wq = (const float*)d_in[1];
    const float* bq = (const float*)d_in[2];
    const float* Wk = (const float*)d_in[3];
    const float* bk = (const float*)d_in[4];
    const float* Wv = (const float*)d_in[5];
    const float* bv = (const float*)d_in[6];
    float* out = (float*)d_out;

    const int B = in_sizes[0] / (kT * kC * kHW);
    cudaFuncSetAttribute(ta_mma, cudaFuncAttributeMaxDynamicSharedMemorySize,
                         kSMEM);
    dim3 grid(kHW / kPIX, B);
    ta_mma<<<grid, kTHREADS, kSMEM>>>(x, Wq, bq, Wk, bk, Wv, bv, out);
}